// round 8
// baseline (speedup 1.0000x reference)
#include <cuda_runtime.h>
#include <math.h>
#include <stdint.h>

#define NMAX   100000
#define EMAX   600000
#define HIDDIM 128

// Scratch (device globals)
__device__ float g_deg[NMAX];
__device__ float g_dinv[NMAX];
__device__ int   g_head[NMAX];
__device__ int   g_next[EMAX];
__device__ float g_h  [(size_t)NMAX * HIDDIM];
__device__ float g_agg[(size_t)NMAX * HIDDIM];
__device__ float g_pooled[HIDDIM];

__device__ __forceinline__ float elu1(float x) { return x > 0.0f ? x : expm1f(x); }
__device__ __forceinline__ float tf32rna(float x) {
    float r; asm("cvt.rna.tf32.f32 %0, %1;" : "=f"(r) : "f"(x)); return r;
}

// ---------------------------------------------------------------------------
__global__ void k_init(int N)
{
    int i = blockIdx.x * blockDim.x + threadIdx.x;
    if (i < N) { g_deg[i] = 1.0f; g_head[i] = -1; }
    if (blockIdx.x == 0 && threadIdx.x < HIDDIM) g_pooled[threadIdx.x] = 0.0f;
}

__global__ void k_lbuild(const int* __restrict__ col, int E, int N)
{
    int e = blockIdx.x * blockDim.x + threadIdx.x;
    if (e < E) {
        unsigned c = (unsigned)col[e];
        if (c < (unsigned)N) {
            g_next[e] = atomicExch(&g_head[c], e);
            atomicAdd(&g_deg[c], 1.0f);
        }
    }
}

__global__ void k_dinv(int N)
{
    int i = blockIdx.x * blockDim.x + threadIdx.x;
    if (i < N) g_dinv[i] = rsqrtf(g_deg[i]);
}

// ---------------------------------------------------------------------------
// Tensor-core GEMM via legacy mma.sync (compute_103-baseline-safe):
//   H = ACT(Xsrc) @ (W_hi + W_lo),  tile 128x128, K chunked by 64.
//
// Smem layout (per row of 64 floats): k packed in pair order (k, k+4) so each
// thread's MMA fragment is ONE LDS.64; 8-byte units XOR-swizzled with
// ((row&7)<<2) and row stride 34 float2 (272B) => fragment loads verified
// bank-conflict-free for all k-steps.

#define KC       64
#define ROW_F2   34                    // float2 stride per row
#define ROW_F    (ROW_F2 * 2)          // float stride per row (68)
#define TILE_F   (128 * ROW_F)         // floats per tile (8704)
#define SMEM_DYN (3 * TILE_F * 4)      // 104448 bytes

// float index for (row r, k in [0,64)) in pair-packed swizzled layout
__device__ __forceinline__ int sw_f(int r, int k)
{
    int u = (k >> 3) * 4 + (k & 3);          // 8-byte unit before swizzle
    u ^= (r & 7) << 2;                       // swizzle
    return r * ROW_F + u * 2 + ((k >> 2) & 1);
}

__device__ __forceinline__ void mma_tf32(float* d, uint32_t a0, uint32_t a1,
                                         uint32_t a2, uint32_t a3,
                                         uint32_t b0, uint32_t b1)
{
    asm volatile(
        "mma.sync.aligned.m16n8k8.row.col.f32.tf32.tf32.f32 "
        "{%0,%1,%2,%3}, {%4,%5,%6,%7}, {%8,%9}, {%0,%1,%2,%3};"
        : "+f"(d[0]), "+f"(d[1]), "+f"(d[2]), "+f"(d[3])
        : "r"(a0), "r"(a1), "r"(a2), "r"(a3), "r"(b0), "r"(b1));
}

__global__ __launch_bounds__(256, 2) void k_gemm_mma(const float* __restrict__ Xin,
                                                     int layer,
                                                     const float* __restrict__ bprev,
                                                     const float* __restrict__ W,
                                                     int N)
{
    extern __shared__ float smf[];
    float* Xs = smf;                   // 128 x 64 (A chunk)
    float* Bh = smf + TILE_F;          // 128 x 64 (W^T hi)
    float* Bl = smf + 2 * TILE_F;      // 128 x 64 (W^T lo)

    const int t    = threadIdx.x;
    const int lane = t & 31;
    const int wid  = t >> 5;
    const int l3   = lane & 3;
    const int q    = lane >> 2;
    const int warp_m = (wid & 3) * 32;   // 4 warps down
    const int warp_n = (wid >> 2) * 64;  // 2 warps across
    const int node0 = blockIdx.x * 128;

    float acc[2][8][4];
#pragma unroll
    for (int i = 0; i < 2; i++)
#pragma unroll
        for (int j = 0; j < 8; j++)
#pragma unroll
            for (int p = 0; p < 4; p++) acc[i][j][p] = 0.0f;

    for (int kc = 0; kc < 2; kc++) {
        const int k0g = kc * KC;

        // ---- stage X chunk: 128 rows x 16 float4 (fused ELU for layer>0) ----
        for (int idx = t; idx < 128 * 16; idx += 256) {
            int m = idx >> 4, k4 = idx & 15;
            int gn = node0 + m;
            float4 v = make_float4(0.f, 0.f, 0.f, 0.f);
            if (gn < N) {
                if (layer == 0) {
                    v = *(const float4*)(Xin + (size_t)gn * 128 + k0g + k4 * 4);
                } else {
                    float4 a = *(const float4*)(g_agg + (size_t)gn * 128 + k0g + k4 * 4);
                    float4 bb = *(const float4*)(bprev + k0g + k4 * 4);
                    v.x = elu1(a.x + bb.x); v.y = elu1(a.y + bb.y);
                    v.z = elu1(a.z + bb.z); v.w = elu1(a.w + bb.w);
                }
                v.x = tf32rna(v.x); v.y = tf32rna(v.y);
                v.z = tf32rna(v.z); v.w = tf32rna(v.w);
            }
            int kb = k4 * 4;
            Xs[sw_f(m, kb + 0)] = v.x;
            Xs[sw_f(m, kb + 1)] = v.y;
            Xs[sw_f(m, kb + 2)] = v.z;
            Xs[sw_f(m, kb + 3)] = v.w;
        }

        // ---- stage W chunk transposed + hi/lo split: 64 k x 128 n ----
        for (int idx = t; idx < 64 * 32; idx += 256) {
            int k = idx >> 5, n4 = idx & 31;
            float4 w = *(const float4*)(W + (size_t)(k0g + k) * 128 + n4 * 4);
            float wv[4] = {w.x, w.y, w.z, w.w};
#pragma unroll
            for (int j = 0; j < 4; j++) {
                int n = n4 * 4 + j;
                float hi = tf32rna(wv[j]);
                float lo = tf32rna(wv[j] - hi);
                int off = sw_f(n, k);
                Bh[off] = hi;
                Bl[off] = lo;
            }
        }
        __syncthreads();

        const float2* X2 = (const float2*)Xs;
        const float2* H2 = (const float2*)Bh;
        const float2* L2 = (const float2*)Bl;
        const int mA = warp_m + q;
        const int nB = warp_n + q;

        // ---- compute: 8 k-steps of 8 ----
#pragma unroll
        for (int ks = 0; ks < 8; ks++) {
            const int uoff = (ks * 4 + l3) ^ (q << 2);   // same for all rows

            float2 xa0 = X2[(mA +  0) * ROW_F2 + uoff];
            float2 xa1 = X2[(mA +  8) * ROW_F2 + uoff];
            float2 xa2 = X2[(mA + 16) * ROW_F2 + uoff];
            float2 xa3 = X2[(mA + 24) * ROW_F2 + uoff];
            uint32_t a00 = __float_as_uint(xa0.x), a01 = __float_as_uint(xa1.x);
            uint32_t a02 = __float_as_uint(xa0.y), a03 = __float_as_uint(xa1.y);
            uint32_t a10 = __float_as_uint(xa2.x), a11 = __float_as_uint(xa3.x);
            uint32_t a12 = __float_as_uint(xa2.y), a13 = __float_as_uint(xa3.y);

            float2 bh[8];
#pragma unroll
            for (int na = 0; na < 8; na++)
                bh[na] = H2[(nB + na * 8) * ROW_F2 + uoff];

            // 16 independent hi MMAs
#pragma unroll
            for (int na = 0; na < 8; na++) {
                uint32_t b0 = __float_as_uint(bh[na].x);
                uint32_t b1 = __float_as_uint(bh[na].y);
                mma_tf32(acc[0][na], a00, a01, a02, a03, b0, b1);
                mma_tf32(acc[1][na], a10, a11, a12, a13, b0, b1);
            }

            float2 bl[8];
#pragma unroll
            for (int na = 0; na < 8; na++)
                bl[na] = L2[(nB + na * 8) * ROW_F2 + uoff];

            // 16 lo MMAs (dependent on hi at distance 16 -> latency hidden)
#pragma unroll
            for (int na = 0; na < 8; na++) {
                uint32_t b0 = __float_as_uint(bl[na].x);
                uint32_t b1 = __float_as_uint(bl[na].y);
                mma_tf32(acc[0][na], a00, a01, a02, a03, b0, b1);
                mma_tf32(acc[1][na], a10, a11, a12, a13, b0, b1);
            }
        }
        __syncthreads();
    }

    // ---- epilogue: C fragments -> g_h (coalesced 8B stores) ----
#pragma unroll
    for (int ma = 0; ma < 2; ma++) {
        int m  = node0 + warp_m + ma * 16 + q;
        int m8 = m + 8;
#pragma unroll
        for (int na = 0; na < 8; na++) {
            int n = warp_n + na * 8 + 2 * l3;
            if (m < N)
                *(float2*)(g_h + (size_t)m * 128 + n) =
                    make_float2(acc[ma][na][0], acc[ma][na][1]);
            if (m8 < N)
                *(float2*)(g_h + (size_t)m8 * 128 + n) =
                    make_float2(acc[ma][na][2], acc[ma][na][3]);
        }
    }
}

// ---------------------------------------------------------------------------
// gather aggregation (no atomics): one warp per node v
__global__ void k_gather(const int* __restrict__ row, int N)
{
    int v = (blockIdx.x * blockDim.x + threadIdx.x) >> 5;
    int lane = threadIdx.x & 31;
    if (v >= N) return;

    float dv = g_dinv[v];
    float4 acc = ((const float4*)(g_h + (size_t)v * 128))[lane];
    float d2 = dv * dv;
    acc.x *= d2; acc.y *= d2; acc.z *= d2; acc.w *= d2;

    int e = g_head[v];
    while (e >= 0) {
        unsigned u = (unsigned)row[e];
        if (u < (unsigned)N) {
            float coef = g_dinv[u] * dv;
            float4 hv = ((const float4*)(g_h + (size_t)u * 128))[lane];
            acc.x = fmaf(hv.x, coef, acc.x);
            acc.y = fmaf(hv.y, coef, acc.y);
            acc.z = fmaf(hv.z, coef, acc.z);
            acc.w = fmaf(hv.w, coef, acc.w);
        }
        e = g_next[e];
    }
    ((float4*)(g_agg + (size_t)v * 128))[lane] = acc;
}

// ---------------------------------------------------------------------------
__global__ void k_pool(const float* __restrict__ b2, int N)
{
    int j = threadIdx.x;   // 128 threads
    float bj = b2[j];
    float s = 0.0f;
    for (int n = blockIdx.x; n < N; n += gridDim.x)
        s += elu1(g_agg[(size_t)n * 128 + j] + bj);
    atomicAdd(&g_pooled[j], s);
}

__global__ void k_final(const float* __restrict__ lin_w,
                        const float* __restrict__ lin_b,
                        float* __restrict__ out, int N)
{
    int j = threadIdx.x;
    if (j < 24) {
        float invn = 1.0f / (float)N;
        float s = lin_b[j];
#pragma unroll 8
        for (int k = 0; k < 128; k++)
            s += g_pooled[k] * invn * lin_w[k * 24 + j];
        out[j] = s;
    }
}

// ---------------------------------------------------------------------------
extern "C" void kernel_launch(void* const* d_in, const int* in_sizes, int n_in,
                              void* d_out, int out_size)
{
    // ---- Input identification: exact sizes (unit-agnostic), ignore extras.
    int unit = 1;
    {
        bool has24 = false, has96 = false;
        for (int i = 0; i < n_in; i++) {
            if (in_sizes[i] == 24) has24 = true;
            if (in_sizes[i] == 96) has96 = true;
        }
        if (!has24 && has96) unit = 4;
    }

    const float* x = nullptr;  const int* eidx = nullptr;
    const float* Ws[3] = {nullptr,nullptr,nullptr};
    const float* bs[3] = {nullptr,nullptr,nullptr};
    const float* lin_w = nullptr; const float* lin_b = nullptr;
    int iW = 0, ib = 0;

    for (int i = 0; i < n_in; i++) {
        long s = (long)in_sizes[i] / unit;
        if      (s == 12800000 && !x)      x     = (const float*)d_in[i];
        else if (s == 1200000  && !eidx)   eidx  = (const int*)  d_in[i];
        else if (s == 16384 && iW < 3)     Ws[iW++] = (const float*)d_in[i];
        else if (s == 3072  && !lin_w)     lin_w = (const float*)d_in[i];
        else if (s == 128   && ib < 3)     bs[ib++] = (const float*)d_in[i];
        else if (s == 24    && !lin_b)     lin_b = (const float*)d_in[i];
    }
    if (!x || !eidx || iW < 3 || ib < 3 || !lin_w || !lin_b) {
        int order[32];
        int m = (n_in < 32) ? n_in : 32;
        for (int i = 0; i < m; i++) order[i] = i;
        for (int i = 0; i < m; i++) {
            int best = i;
            for (int j = i + 1; j < m; j++)
                if (in_sizes[order[j]] > in_sizes[order[best]]) best = j;
            int tmp = order[best];
            for (int j = best; j > i; j--) order[j] = order[j - 1];
            order[i] = tmp;
        }
        if (m < 10) return;
        x     = (const float*)d_in[order[0]];
        eidx  = (const int*)  d_in[order[1]];
        Ws[0] = (const float*)d_in[order[2]];
        Ws[1] = (const float*)d_in[order[3]];
        Ws[2] = (const float*)d_in[order[4]];
        lin_w = (const float*)d_in[order[5]];
        bs[0] = (const float*)d_in[order[6]];
        bs[1] = (const float*)d_in[order[7]];
        bs[2] = (const float*)d_in[order[8]];
        lin_b = (const float*)d_in[order[9]];
    }
    float* out = (float*)d_out;

    const int N = 100000;
    const int E = 600000;
    const int* e_row = eidx;
    const int* e_col = eidx + E;

    cudaFuncSetAttribute(k_gemm_mma,
                         cudaFuncAttributeMaxDynamicSharedMemorySize, SMEM_DYN);

    k_init<<<(N + 255) / 256, 256>>>(N);
    k_lbuild<<<(E + 255) / 256, 256>>>(e_col, E, N);
    k_dinv<<<(N + 255) / 256, 256>>>(N);

    const int tc_blocks     = (N + 127) / 128;   // 782
    const int gather_blocks = (N + 7) / 8;

    for (int l = 0; l < 3; l++) {
        k_gemm_mma<<<tc_blocks, 256, SMEM_DYN>>>(x, l, l > 0 ? bs[l - 1] : nullptr,
                                                 Ws[l], N);
        k_gather<<<gather_blocks, 256>>>(e_row, N);
    }

    k_pool<<<512, 128>>>(bs[2], N);
    k_final<<<1, 32>>>(lin_w, lin_b, out, N);
}

// round 9
// speedup vs baseline: 1.0066x; 1.0066x over previous
#include <cuda_runtime.h>
#include <math.h>
#include <stdint.h>

#define NMAX   100000
#define EMAX   600000
#define HIDDIM 128
#define NBLK   ((NMAX + 255) / 256)   // 391 scan blocks

// Scratch (device globals)
__device__ int   g_degi[NMAX];     // incoming-edge count (no self loop)
__device__ int   g_loc[NMAX];      // block-local exclusive scan
__device__ int   g_bsum[NBLK];     // per-block sums -> exclusive-scanned
__device__ int   g_off[NMAX];      // CSR offsets
__device__ int   g_cursor[NMAX];   // fill cursors
__device__ int   g_csr[EMAX];      // CSR: source node per incoming edge
__device__ float g_dinv[NMAX];
__device__ float g_h  [(size_t)NMAX * HIDDIM];
__device__ float g_agg[(size_t)NMAX * HIDDIM];
__device__ float g_pooled[HIDDIM];

__device__ __forceinline__ float elu1(float x) { return x > 0.0f ? x : expm1f(x); }
__device__ __forceinline__ float tf32rna(float x) {
    float r; asm("cvt.rna.tf32.f32 %0, %1;" : "=f"(r) : "f"(x)); return r;
}

// ---------------------------------------------------------------------------
__global__ void k_init(int N)
{
    int i = blockIdx.x * blockDim.x + threadIdx.x;
    if (i < N) g_degi[i] = 0;
    if (blockIdx.x == 0 && threadIdx.x < HIDDIM) g_pooled[threadIdx.x] = 0.0f;
}

__global__ void k_count(const int* __restrict__ col, int E, int N)
{
    int e = blockIdx.x * blockDim.x + threadIdx.x;
    if (e < E) {
        unsigned c = (unsigned)col[e];
        if (c < (unsigned)N) atomicAdd(&g_degi[c], 1);
    }
}

// block-local exclusive scan (256/block) + block totals
__global__ void k_scan_a(int N)
{
    __shared__ int s[256];
    int tid = threadIdx.x;
    int i = blockIdx.x * 256 + tid;
    int v = (i < N) ? g_degi[i] : 0;
    s[tid] = v;
    __syncthreads();
    int acc = v;
#pragma unroll
    for (int d = 1; d < 256; d <<= 1) {
        int add = (tid >= d) ? s[tid - d] : 0;
        __syncthreads();
        acc += add;
        s[tid] = acc;
        __syncthreads();
    }
    if (i < N) g_loc[i] = acc - v;            // exclusive
    if (tid == 255) g_bsum[blockIdx.x] = acc; // block total
}

// scan the 391 block sums (single block, 512 threads)
__global__ void k_scan_b(void)
{
    __shared__ int s[512];
    int tid = threadIdx.x;
    int v = (tid < NBLK) ? g_bsum[tid] : 0;
    s[tid] = v;
    __syncthreads();
    int acc = v;
#pragma unroll
    for (int d = 1; d < 512; d <<= 1) {
        int add = (tid >= d) ? s[tid - d] : 0;
        __syncthreads();
        acc += add;
        s[tid] = acc;
        __syncthreads();
    }
    if (tid < NBLK) g_bsum[tid] = acc - v;    // exclusive
}

// offsets, cursors, dinv
__global__ void k_scan_c(int N)
{
    int i = blockIdx.x * blockDim.x + threadIdx.x;
    if (i < N) {
        int o = g_loc[i] + g_bsum[i >> 8];
        g_off[i] = o;
        g_cursor[i] = o;
        g_dinv[i] = rsqrtf(1.0f + (float)g_degi[i]);
    }
}

__global__ void k_fill(const int* __restrict__ row,
                       const int* __restrict__ col, int E, int N)
{
    int e = blockIdx.x * blockDim.x + threadIdx.x;
    if (e < E) {
        unsigned c = (unsigned)col[e];
        if (c < (unsigned)N) {
            int pos = atomicAdd(&g_cursor[c], 1);
            g_csr[pos] = row[e];
        }
    }
}

// ---------------------------------------------------------------------------
// Tensor-core GEMM via legacy mma.sync (compute_103-baseline-safe):
//   H = ACT(Xsrc) @ (W_hi + W_lo),  tile 128x128, K chunked by 64.
// 512 threads, 16 warps in 4x4 grid, warp tile 32m x 32n -> acc = 32 regs.
// Pair-packed XOR-swizzled smem (row stride 34 float2), fragment = 1 LDS.64.

#define KC       64
#define ROW_F2   34
#define ROW_F    (ROW_F2 * 2)
#define TILE_F   (128 * ROW_F)
#define SMEM_DYN (3 * TILE_F * 4)      // 104448 bytes

__device__ __forceinline__ int sw_f(int r, int k)
{
    int u = (k >> 3) * 4 + (k & 3);
    u ^= (r & 7) << 2;
    return r * ROW_F + u * 2 + ((k >> 2) & 1);
}

__device__ __forceinline__ void mma_tf32(float* d, uint32_t a0, uint32_t a1,
                                         uint32_t a2, uint32_t a3,
                                         uint32_t b0, uint32_t b1)
{
    asm volatile(
        "mma.sync.aligned.m16n8k8.row.col.f32.tf32.tf32.f32 "
        "{%0,%1,%2,%3}, {%4,%5,%6,%7}, {%8,%9}, {%0,%1,%2,%3};"
        : "+f"(d[0]), "+f"(d[1]), "+f"(d[2]), "+f"(d[3])
        : "r"(a0), "r"(a1), "r"(a2), "r"(a3), "r"(b0), "r"(b1));
}

__global__ __launch_bounds__(512, 2) void k_gemm_mma(const float* __restrict__ Xin,
                                                     int layer,
                                                     const float* __restrict__ bprev,
                                                     const float* __restrict__ W,
                                                     int N)
{
    extern __shared__ float smf[];
    float* Xs = smf;
    float* Bh = smf + TILE_F;
    float* Bl = smf + 2 * TILE_F;

    const int t    = threadIdx.x;
    const int lane = t & 31;
    const int wid  = t >> 5;
    const int l3   = lane & 3;
    const int q    = lane >> 2;
    const int warp_m = (wid & 3) * 32;   // 4 warps down
    const int warp_n = (wid >> 2) * 32;  // 4 warps across
    const int node0 = blockIdx.x * 128;

    float acc[2][4][4];
#pragma unroll
    for (int i = 0; i < 2; i++)
#pragma unroll
        for (int j = 0; j < 4; j++)
#pragma unroll
            for (int p = 0; p < 4; p++) acc[i][j][p] = 0.0f;

    for (int kc = 0; kc < 2; kc++) {
        const int k0g = kc * KC;

        // ---- stage X chunk: 128 rows x 16 float4 (fused ELU for layer>0) ----
        for (int idx = t; idx < 128 * 16; idx += 512) {
            int m = idx >> 4, k4 = idx & 15;
            int gn = node0 + m;
            float4 v = make_float4(0.f, 0.f, 0.f, 0.f);
            if (gn < N) {
                if (layer == 0) {
                    v = *(const float4*)(Xin + (size_t)gn * 128 + k0g + k4 * 4);
                } else {
                    float4 a = *(const float4*)(g_agg + (size_t)gn * 128 + k0g + k4 * 4);
                    float4 bb = *(const float4*)(bprev + k0g + k4 * 4);
                    v.x = elu1(a.x + bb.x); v.y = elu1(a.y + bb.y);
                    v.z = elu1(a.z + bb.z); v.w = elu1(a.w + bb.w);
                }
                v.x = tf32rna(v.x); v.y = tf32rna(v.y);
                v.z = tf32rna(v.z); v.w = tf32rna(v.w);
            }
            int kb = k4 * 4;
            Xs[sw_f(m, kb + 0)] = v.x;
            Xs[sw_f(m, kb + 1)] = v.y;
            Xs[sw_f(m, kb + 2)] = v.z;
            Xs[sw_f(m, kb + 3)] = v.w;
        }

        // ---- stage W chunk transposed + hi/lo split: 64 k x 128 n ----
        for (int idx = t; idx < 64 * 32; idx += 512) {
            int k = idx >> 5, n4 = idx & 31;
            float4 w = *(const float4*)(W + (size_t)(k0g + k) * 128 + n4 * 4);
            float wv[4] = {w.x, w.y, w.z, w.w};
#pragma unroll
            for (int j = 0; j < 4; j++) {
                int n = n4 * 4 + j;
                float hi = tf32rna(wv[j]);
                float lo = tf32rna(wv[j] - hi);
                int off = sw_f(n, k);
                Bh[off] = hi;
                Bl[off] = lo;
            }
        }
        __syncthreads();

        const float2* XA = (const float2*)Xs + (warp_m + q) * ROW_F2;
        const float2* HB = (const float2*)Bh + (warp_n + q) * ROW_F2;
        const float2* LB = (const float2*)Bl + (warp_n + q) * ROW_F2;

        // ---- compute: 8 k-steps of 8 ----
#pragma unroll
        for (int ks = 0; ks < 8; ks++) {
            const int uoff = (ks * 4 + l3) ^ (q << 2);

            float2 xa0 = XA[ 0 * ROW_F2 + uoff];
            float2 xa1 = XA[ 8 * ROW_F2 + uoff];
            float2 xa2 = XA[16 * ROW_F2 + uoff];
            float2 xa3 = XA[24 * ROW_F2 + uoff];
            uint32_t a00 = __float_as_uint(xa0.x), a01 = __float_as_uint(xa1.x);
            uint32_t a02 = __float_as_uint(xa0.y), a03 = __float_as_uint(xa1.y);
            uint32_t a10 = __float_as_uint(xa2.x), a11 = __float_as_uint(xa3.x);
            uint32_t a12 = __float_as_uint(xa2.y), a13 = __float_as_uint(xa3.y);

            // hi phase (8 MMAs), then lo phase (8 MMAs): RAW distance 8
#pragma unroll
            for (int na = 0; na < 4; na++) {
                float2 b = HB[na * 8 * ROW_F2 + uoff];
                uint32_t b0 = __float_as_uint(b.x), b1 = __float_as_uint(b.y);
                mma_tf32(acc[0][na], a00, a01, a02, a03, b0, b1);
                mma_tf32(acc[1][na], a10, a11, a12, a13, b0, b1);
            }
#pragma unroll
            for (int na = 0; na < 4; na++) {
                float2 b = LB[na * 8 * ROW_F2 + uoff];
                uint32_t b0 = __float_as_uint(b.x), b1 = __float_as_uint(b.y);
                mma_tf32(acc[0][na], a00, a01, a02, a03, b0, b1);
                mma_tf32(acc[1][na], a10, a11, a12, a13, b0, b1);
            }
        }
        __syncthreads();
    }

    // ---- epilogue: C fragments -> g_h (coalesced 8B stores) ----
#pragma unroll
    for (int ma = 0; ma < 2; ma++) {
        int m  = node0 + warp_m + ma * 16 + q;
        int m8 = m + 8;
#pragma unroll
        for (int na = 0; na < 4; na++) {
            int n = warp_n + na * 8 + 2 * l3;
            if (m < N)
                *(float2*)(g_h + (size_t)m * 128 + n) =
                    make_float2(acc[ma][na][0], acc[ma][na][1]);
            if (m8 < N)
                *(float2*)(g_h + (size_t)m8 * 128 + n) =
                    make_float2(acc[ma][na][2], acc[ma][na][3]);
        }
    }
}

// ---------------------------------------------------------------------------
// CSR gather (no atomics, no pointer chase): one warp per node v.
// Lanes pre-load <=32 edge ids + coefs in parallel, shfl-broadcast, then all
// row reads issue with full MLP.
__global__ void k_gather(int N)
{
    int v = (blockIdx.x * blockDim.x + threadIdx.x) >> 5;
    int lane = threadIdx.x & 31;
    if (v >= N) return;

    float dv = g_dinv[v];
    float4 acc = ((const float4*)(g_h + (size_t)v * 128))[lane];
    float d2 = dv * dv;
    acc.x *= d2; acc.y *= d2; acc.z *= d2; acc.w *= d2;

    int start = g_off[v];
    int remaining = g_degi[v];
    while (remaining > 0) {
        int cnt = remaining < 32 ? remaining : 32;
        int u = 0; float cf = 0.0f;
        if (lane < cnt) {
            int uu = g_csr[start + lane];
            if ((unsigned)uu < (unsigned)N) { u = uu; cf = g_dinv[uu] * dv; }
        }
        for (int j = 0; j < cnt; j++) {
            int   uj = __shfl_sync(0xFFFFFFFFu, u, j);
            float cj = __shfl_sync(0xFFFFFFFFu, cf, j);
            float4 hv = ((const float4*)(g_h + (size_t)uj * 128))[lane];
            acc.x = fmaf(hv.x, cj, acc.x);
            acc.y = fmaf(hv.y, cj, acc.y);
            acc.z = fmaf(hv.z, cj, acc.z);
            acc.w = fmaf(hv.w, cj, acc.w);
        }
        start += cnt; remaining -= cnt;
    }
    ((float4*)(g_agg + (size_t)v * 128))[lane] = acc;
}

// ---------------------------------------------------------------------------
__global__ void k_pool(const float* __restrict__ b2, int N)
{
    int j = threadIdx.x;   // 128 threads
    float bj = b2[j];
    float s = 0.0f;
    for (int n = blockIdx.x; n < N; n += gridDim.x)
        s += elu1(g_agg[(size_t)n * 128 + j] + bj);
    atomicAdd(&g_pooled[j], s);
}

__global__ void k_final(const float* __restrict__ lin_w,
                        const float* __restrict__ lin_b,
                        float* __restrict__ out, int N)
{
    int j = threadIdx.x;
    if (j < 24) {
        float invn = 1.0f / (float)N;
        float s = lin_b[j];
#pragma unroll 8
        for (int k = 0; k < 128; k++)
            s += g_pooled[k] * invn * lin_w[k * 24 + j];
        out[j] = s;
    }
}

// ---------------------------------------------------------------------------
extern "C" void kernel_launch(void* const* d_in, const int* in_sizes, int n_in,
                              void* d_out, int out_size)
{
    // ---- Input identification: exact sizes (unit-agnostic), ignore extras.
    int unit = 1;
    {
        bool has24 = false, has96 = false;
        for (int i = 0; i < n_in; i++) {
            if (in_sizes[i] == 24) has24 = true;
            if (in_sizes[i] == 96) has96 = true;
        }
        if (!has24 && has96) unit = 4;
    }

    const float* x = nullptr;  const int* eidx = nullptr;
    const float* Ws[3] = {nullptr,nullptr,nullptr};
    const float* bs[3] = {nullptr,nullptr,nullptr};
    const float* lin_w = nullptr; const float* lin_b = nullptr;
    int iW = 0, ib = 0;

    for (int i = 0; i < n_in; i++) {
        long s = (long)in_sizes[i] / unit;
        if      (s == 12800000 && !x)      x     = (const float*)d_in[i];
        else if (s == 1200000  && !eidx)   eidx  = (const int*)  d_in[i];
        else if (s == 16384 && iW < 3)     Ws[iW++] = (const float*)d_in[i];
        else if (s == 3072  && !lin_w)     lin_w = (const float*)d_in[i];
        else if (s == 128   && ib < 3)     bs[ib++] = (const float*)d_in[i];
        else if (s == 24    && !lin_b)     lin_b = (const float*)d_in[i];
    }
    if (!x || !eidx || iW < 3 || ib < 3 || !lin_w || !lin_b) {
        int order[32];
        int m = (n_in < 32) ? n_in : 32;
        for (int i = 0; i < m; i++) order[i] = i;
        for (int i = 0; i < m; i++) {
            int best = i;
            for (int j = i + 1; j < m; j++)
                if (in_sizes[order[j]] > in_sizes[order[best]]) best = j;
            int tmp = order[best];
            for (int j = best; j > i; j--) order[j] = order[j - 1];
            order[i] = tmp;
        }
        if (m < 10) return;
        x     = (const float*)d_in[order[0]];
        eidx  = (const int*)  d_in[order[1]];
        Ws[0] = (const float*)d_in[order[2]];
        Ws[1] = (const float*)d_in[order[3]];
        Ws[2] = (const float*)d_in[order[4]];
        lin_w = (const float*)d_in[order[5]];
        bs[0] = (const float*)d_in[order[6]];
        bs[1] = (const float*)d_in[order[7]];
        bs[2] = (const float*)d_in[order[8]];
        lin_b = (const float*)d_in[order[9]];
    }
    float* out = (float*)d_out;

    const int N = 100000;
    const int E = 600000;
    const int* e_row = eidx;
    const int* e_col = eidx + E;

    cudaFuncSetAttribute(k_gemm_mma,
                         cudaFuncAttributeMaxDynamicSharedMemorySize, SMEM_DYN);

    // CSR build
    k_init<<<(N + 255) / 256, 256>>>(N);
    k_count<<<(E + 255) / 256, 256>>>(e_col, E, N);
    k_scan_a<<<NBLK, 256>>>(N);
    k_scan_b<<<1, 512>>>();
    k_scan_c<<<(N + 255) / 256, 256>>>(N);
    k_fill<<<(E + 255) / 256, 256>>>(e_row, e_col, E, N);

    const int tc_blocks     = (N + 127) / 128;   // 782
    const int gather_blocks = (N + 7) / 8;

    for (int l = 0; l < 3; l++) {
        k_gemm_mma<<<tc_blocks, 512, SMEM_DYN>>>(x, l, l > 0 ? bs[l - 1] : nullptr,
                                                 Ws[l], N);
        k_gather<<<gather_blocks, 256>>>(N);
    }

    k_pool<<<512, 128>>>(bs[2], N);
    k_final<<<1, 32>>>(lin_w, lin_b, out, N);
}

// round 10
// speedup vs baseline: 1.0877x; 1.0807x over previous
#include <cuda_runtime.h>
#include <math.h>
#include <stdint.h>

#define NMAX   100000
#define EMAX   600000
#define HIDDIM 128
#define NBLK   ((NMAX + 255) / 256)   // 391 scan blocks

typedef unsigned long long ull;

// Scratch (device globals)
__device__ int   g_degi[NMAX];
__device__ int   g_loc[NMAX];
__device__ int   g_bsum[NBLK];
__device__ int   g_off[NMAX];
__device__ int   g_cursor[NMAX];
__device__ int   g_csr[EMAX];
__device__ float g_dinv[NMAX];
__device__ float g_h  [(size_t)NMAX * HIDDIM];
__device__ float g_agg[(size_t)NMAX * HIDDIM];
__device__ float g_pooled[HIDDIM];

__device__ __forceinline__ float elu1(float x) { return x > 0.0f ? x : expm1f(x); }

// packed f32x2 fma: d = a*b + d   (sm_100+ baseline PTX)
__device__ __forceinline__ void fma2(ull& d, ull a, ull b)
{
    asm("fma.rn.f32x2 %0, %1, %2, %0;" : "+l"(d) : "l"(a), "l"(b));
}
__device__ __forceinline__ ull dupf(float x)
{
    unsigned u = __float_as_uint(x);
    return ((ull)u << 32) | u;
}

// ---------------------------------------------------------------------------
__global__ void k_init(int N)
{
    int i = blockIdx.x * blockDim.x + threadIdx.x;
    if (i < N) g_degi[i] = 0;
    if (blockIdx.x == 0 && threadIdx.x < HIDDIM) g_pooled[threadIdx.x] = 0.0f;
}

__global__ void k_count(const int* __restrict__ col, int E, int N)
{
    int e = blockIdx.x * blockDim.x + threadIdx.x;
    if (e < E) {
        unsigned c = (unsigned)col[e];
        if (c < (unsigned)N) atomicAdd(&g_degi[c], 1);
    }
}

__global__ void k_scan_a(int N)
{
    __shared__ int s[256];
    int tid = threadIdx.x;
    int i = blockIdx.x * 256 + tid;
    int v = (i < N) ? g_degi[i] : 0;
    s[tid] = v;
    __syncthreads();
    int acc = v;
#pragma unroll
    for (int d = 1; d < 256; d <<= 1) {
        int add = (tid >= d) ? s[tid - d] : 0;
        __syncthreads();
        acc += add;
        s[tid] = acc;
        __syncthreads();
    }
    if (i < N) g_loc[i] = acc - v;
    if (tid == 255) g_bsum[blockIdx.x] = acc;
}

__global__ void k_scan_b(void)
{
    __shared__ int s[512];
    int tid = threadIdx.x;
    int v = (tid < NBLK) ? g_bsum[tid] : 0;
    s[tid] = v;
    __syncthreads();
    int acc = v;
#pragma unroll
    for (int d = 1; d < 512; d <<= 1) {
        int add = (tid >= d) ? s[tid - d] : 0;
        __syncthreads();
        acc += add;
        s[tid] = acc;
        __syncthreads();
    }
    if (tid < NBLK) g_bsum[tid] = acc - v;
}

__global__ void k_scan_c(int N)
{
    int i = blockIdx.x * blockDim.x + threadIdx.x;
    if (i < N) {
        int o = g_loc[i] + g_bsum[i >> 8];
        g_off[i] = o;
        g_cursor[i] = o;
        g_dinv[i] = rsqrtf(1.0f + (float)g_degi[i]);
    }
}

__global__ void k_fill(const int* __restrict__ row,
                       const int* __restrict__ col, int E, int N)
{
    int e = blockIdx.x * blockDim.x + threadIdx.x;
    if (e < E) {
        unsigned c = (unsigned)col[e];
        if (c < (unsigned)N) {
            int pos = atomicAdd(&g_cursor[c], 1);
            g_csr[pos] = row[e];
        }
    }
}

// ---------------------------------------------------------------------------
// GEMM  H = ACT(Xsrc) @ W  via packed fma.rn.f32x2 (2 FMAs/instr).
// Tile 64 nodes x 128 cols, 256 threads, K chunked by 64.
// smem: Ws 64x128 f32 (32KB, float4-pair friendly) + Xdup 64x64 (x,x)-pairs
// (32KB). Inner loop: 2+8 LDS.64 + 16 FFMA2 per kk -> FMA-pipe bound.
#define GSM_W  0
#define GSM_X  32768
#define GSM_DYN 65536

__global__ __launch_bounds__(256) void k_gemm(const float* __restrict__ Xin,
                                              int layer,
                                              const float* __restrict__ bprev,
                                              const float* __restrict__ W,
                                              int N)
{
    extern __shared__ char sm[];
    const int t = threadIdx.x;
    const int c = t & 31;      // column group (4 cols)
    const int r = t >> 5;      // node group (8 nodes)
    const int node0 = blockIdx.x * 64;

    ull acc01[8], acc23[8];
#pragma unroll
    for (int i = 0; i < 8; i++) { acc01[i] = 0ull; acc23[i] = 0ull; }

    for (int k0 = 0; k0 < 128; k0 += 64) {
        // stage W chunk (64 rows x 128 cols), coalesced float4
        {
            const float4* src = (const float4*)(W + (size_t)k0 * 128);
            float4* dst = (float4*)(sm + GSM_W);
            for (int q = t; q < 64 * 32; q += 256) dst[q] = src[q];
        }
        // stage X tile duplicated: (x,x) pairs, fused bias+ELU for layer>0
        {
            ull* Xd = (ull*)(sm + GSM_X);
            for (int q = t; q < 64 * 16; q += 256) {
                int n = q >> 4, kq = q & 15;
                int gn = node0 + n;
                float4 v = make_float4(0.f, 0.f, 0.f, 0.f);
                if (gn < N) {
                    if (layer == 0) {
                        v = *(const float4*)(Xin + (size_t)gn * 128 + k0 + kq * 4);
                    } else {
                        float4 a = *(const float4*)(g_agg + (size_t)gn * 128 + k0 + kq * 4);
                        float4 bb = *(const float4*)(bprev + k0 + kq * 4);
                        v.x = elu1(a.x + bb.x); v.y = elu1(a.y + bb.y);
                        v.z = elu1(a.z + bb.z); v.w = elu1(a.w + bb.w);
                    }
                }
                int base = n * 64 + kq * 4;
                Xd[base + 0] = dupf(v.x);
                Xd[base + 1] = dupf(v.y);
                Xd[base + 2] = dupf(v.z);
                Xd[base + 3] = dupf(v.w);
            }
        }
        __syncthreads();

        const ull* W2 = (const ull*)(sm + GSM_W);   // [64][64] pairs
        const ull* Xd = (const ull*)(sm + GSM_X);   // [64][64] dup pairs

#pragma unroll 4
        for (int kk = 0; kk < 64; kk++) {
            ull w01 = W2[kk * 64 + c * 2];
            ull w23 = W2[kk * 64 + c * 2 + 1];
            const ull* xr = Xd + (r * 8) * 64 + kk;
#pragma unroll
            for (int i = 0; i < 8; i++) {
                ull xx = xr[i * 64];                 // warp-broadcast LDS.64
                fma2(acc01[i], xx, w01);
                fma2(acc23[i], xx, w23);
            }
        }
        __syncthreads();
    }

    // epilogue: unpack -> g_h
#pragma unroll
    for (int i = 0; i < 8; i++) {
        int gn = node0 + r * 8 + i;
        if (gn < N) {
            float4 v = make_float4(
                __uint_as_float((unsigned)(acc01[i] & 0xffffffffu)),
                __uint_as_float((unsigned)(acc01[i] >> 32)),
                __uint_as_float((unsigned)(acc23[i] & 0xffffffffu)),
                __uint_as_float((unsigned)(acc23[i] >> 32)));
            *(float4*)(g_h + (size_t)gn * 128 + c * 4) = v;
        }
    }
}

// ---------------------------------------------------------------------------
// CSR gather: one warp per node, parallel edge preload + shfl broadcast
__global__ void k_gather(int N)
{
    int v = (blockIdx.x * blockDim.x + threadIdx.x) >> 5;
    int lane = threadIdx.x & 31;
    if (v >= N) return;

    float dv = g_dinv[v];
    float4 acc = ((const float4*)(g_h + (size_t)v * 128))[lane];
    float d2 = dv * dv;
    acc.x *= d2; acc.y *= d2; acc.z *= d2; acc.w *= d2;

    int start = g_off[v];
    int remaining = g_degi[v];
    while (remaining > 0) {
        int cnt = remaining < 32 ? remaining : 32;
        int u = 0; float cf = 0.0f;
        if (lane < cnt) {
            int uu = g_csr[start + lane];
            if ((unsigned)uu < (unsigned)N) { u = uu; cf = g_dinv[uu] * dv; }
        }
        for (int j = 0; j < cnt; j++) {
            int   uj = __shfl_sync(0xFFFFFFFFu, u, j);
            float cj = __shfl_sync(0xFFFFFFFFu, cf, j);
            float4 hv = ((const float4*)(g_h + (size_t)uj * 128))[lane];
            acc.x = fmaf(hv.x, cj, acc.x);
            acc.y = fmaf(hv.y, cj, acc.y);
            acc.z = fmaf(hv.z, cj, acc.z);
            acc.w = fmaf(hv.w, cj, acc.w);
        }
        start += cnt; remaining -= cnt;
    }
    ((float4*)(g_agg + (size_t)v * 128))[lane] = acc;
}

// ---------------------------------------------------------------------------
__global__ void k_pool(const float* __restrict__ b2, int N)
{
    int j = threadIdx.x;   // 128 threads
    float bj = b2[j];
    float s = 0.0f;
    for (int n = blockIdx.x; n < N; n += gridDim.x)
        s += elu1(g_agg[(size_t)n * 128 + j] + bj);
    atomicAdd(&g_pooled[j], s);
}

__global__ void k_final(const float* __restrict__ lin_w,
                        const float* __restrict__ lin_b,
                        float* __restrict__ out, int N)
{
    int j = threadIdx.x;
    if (j < 24) {
        float invn = 1.0f / (float)N;
        float s = lin_b[j];
#pragma unroll 8
        for (int k = 0; k < 128; k++)
            s += g_pooled[k] * invn * lin_w[k * 24 + j];
        out[j] = s;
    }
}

// ---------------------------------------------------------------------------
extern "C" void kernel_launch(void* const* d_in, const int* in_sizes, int n_in,
                              void* d_out, int out_size)
{
    // ---- Input identification: exact sizes (unit-agnostic), ignore extras.
    int unit = 1;
    {
        bool has24 = false, has96 = false;
        for (int i = 0; i < n_in; i++) {
            if (in_sizes[i] == 24) has24 = true;
            if (in_sizes[i] == 96) has96 = true;
        }
        if (!has24 && has96) unit = 4;
    }

    const float* x = nullptr;  const int* eidx = nullptr;
    const float* Ws[3] = {nullptr,nullptr,nullptr};
    const float* bs[3] = {nullptr,nullptr,nullptr};
    const float* lin_w = nullptr; const float* lin_b = nullptr;
    int iW = 0, ib = 0;

    for (int i = 0; i < n_in; i++) {
        long s = (long)in_sizes[i] / unit;
        if      (s == 12800000 && !x)      x     = (const float*)d_in[i];
        else if (s == 1200000  && !eidx)   eidx  = (const int*)  d_in[i];
        else if (s == 16384 && iW < 3)     Ws[iW++] = (const float*)d_in[i];
        else if (s == 3072  && !lin_w)     lin_w = (const float*)d_in[i];
        else if (s == 128   && ib < 3)     bs[ib++] = (const float*)d_in[i];
        else if (s == 24    && !lin_b)     lin_b = (const float*)d_in[i];
    }
    if (!x || !eidx || iW < 3 || ib < 3 || !lin_w || !lin_b) {
        int order[32];
        int m = (n_in < 32) ? n_in : 32;
        for (int i = 0; i < m; i++) order[i] = i;
        for (int i = 0; i < m; i++) {
            int best = i;
            for (int j = i + 1; j < m; j++)
                if (in_sizes[order[j]] > in_sizes[order[best]]) best = j;
            int tmp = order[best];
            for (int j = best; j > i; j--) order[j] = order[j - 1];
            order[i] = tmp;
        }
        if (m < 10) return;
        x     = (const float*)d_in[order[0]];
        eidx  = (const int*)  d_in[order[1]];
        Ws[0] = (const float*)d_in[order[2]];
        Ws[1] = (const float*)d_in[order[3]];
        Ws[2] = (const float*)d_in[order[4]];
        lin_w = (const float*)d_in[order[5]];
        bs[0] = (const float*)d_in[order[6]];
        bs[1] = (const float*)d_in[order[7]];
        bs[2] = (const float*)d_in[order[8]];
        lin_b = (const float*)d_in[order[9]];
    }
    float* out = (float*)d_out;

    const int N = 100000;
    const int E = 600000;
    const int* e_row = eidx;
    const int* e_col = eidx + E;

    cudaFuncSetAttribute(k_gemm,
                         cudaFuncAttributeMaxDynamicSharedMemorySize, GSM_DYN);

    // CSR build
    k_init<<<(N + 255) / 256, 256>>>(N);
    k_count<<<(E + 255) / 256, 256>>>(e_col, E, N);
    k_scan_a<<<NBLK, 256>>>(N);
    k_scan_b<<<1, 512>>>();
    k_scan_c<<<(N + 255) / 256, 256>>>(N);
    k_fill<<<(E + 255) / 256, 256>>>(e_row, e_col, E, N);

    const int gemm_blocks   = (N + 63) / 64;     // 1563
    const int gather_blocks = (N + 7) / 8;

    for (int l = 0; l < 3; l++) {
        k_gemm<<<gemm_blocks, 256, GSM_DYN>>>(x, l, l > 0 ? bs[l - 1] : nullptr,
                                              Ws[l], N);
        k_gather<<<gather_blocks, 256>>>(N);
    }

    k_pool<<<512, 128>>>(bs[2], N);
    k_final<<<1, 32>>>(lin_w, lin_b, out, N);
}

// round 11
// speedup vs baseline: 1.1124x; 1.0226x over previous
#include <cuda_runtime.h>
#include <math.h>
#include <stdint.h>

#define NMAX   100000
#define EMAX   600000
#define HIDDIM 128
#define NBLK   ((NMAX + 255) / 256)   // 391 scan blocks

typedef unsigned long long ull;

// Scratch (device globals)
__device__ int   g_degi[NMAX];
__device__ int   g_loc[NMAX];
__device__ int   g_bsum[NBLK];
__device__ int   g_off[NMAX];
__device__ int   g_cursor[NMAX];
__device__ int   g_csr[EMAX];      // source node per incoming edge
__device__ float g_csrc[EMAX];     // dinv[u]*dinv[v] per incoming edge
__device__ float g_dinv[NMAX];
__device__ float g_h  [(size_t)NMAX * HIDDIM];
__device__ float g_agg[(size_t)NMAX * HIDDIM];
__device__ float g_pooled[HIDDIM];

__device__ __forceinline__ float elu1(float x) { return x > 0.0f ? x : expm1f(x); }

// packed f32x2 fma: d = a*b + d   (sm_100+ baseline PTX)
__device__ __forceinline__ void fma2(ull& d, ull a, ull b)
{
    asm("fma.rn.f32x2 %0, %1, %2, %0;" : "+l"(d) : "l"(a), "l"(b));
}
__device__ __forceinline__ ull dupf(float x)
{
    unsigned u = __float_as_uint(x);
    return ((ull)u << 32) | u;
}

// ---------------------------------------------------------------------------
__global__ void k_count(const int* __restrict__ col, int E, int N)
{
    int e = blockIdx.x * blockDim.x + threadIdx.x;
    if (e < E) {
        unsigned c = (unsigned)col[e];
        if (c < (unsigned)N) atomicAdd(&g_degi[c], 1);
    }
}

__global__ void k_scan_a(int N)
{
    __shared__ int s[256];
    int tid = threadIdx.x;
    int i = blockIdx.x * 256 + tid;
    int v = (i < N) ? g_degi[i] : 0;
    s[tid] = v;
    __syncthreads();
    int acc = v;
#pragma unroll
    for (int d = 1; d < 256; d <<= 1) {
        int add = (tid >= d) ? s[tid - d] : 0;
        __syncthreads();
        acc += add;
        s[tid] = acc;
        __syncthreads();
    }
    if (i < N) g_loc[i] = acc - v;
    if (tid == 255) g_bsum[blockIdx.x] = acc;
}

__global__ void k_scan_b(void)
{
    __shared__ int s[512];
    int tid = threadIdx.x;
    int v = (tid < NBLK) ? g_bsum[tid] : 0;
    s[tid] = v;
    __syncthreads();
    int acc = v;
#pragma unroll
    for (int d = 1; d < 512; d <<= 1) {
        int add = (tid >= d) ? s[tid - d] : 0;
        __syncthreads();
        acc += add;
        s[tid] = acc;
        __syncthreads();
    }
    if (tid < NBLK) g_bsum[tid] = acc - v;
}

__global__ void k_scan_c(int N)
{
    int i = blockIdx.x * blockDim.x + threadIdx.x;
    if (i < N) {
        int o = g_loc[i] + g_bsum[i >> 8];
        g_off[i] = o;
        g_cursor[i] = o;
        g_dinv[i] = rsqrtf(1.0f + (float)g_degi[i]);
    }
}

// fill CSR with source id AND precomputed coefficient (dinv ready here)
__global__ void k_fill(const int* __restrict__ row,
                       const int* __restrict__ col, int E, int N)
{
    int e = blockIdx.x * blockDim.x + threadIdx.x;
    if (e < E) {
        unsigned c = (unsigned)col[e];
        if (c < (unsigned)N) {
            int pos = atomicAdd(&g_cursor[c], 1);
            unsigned r = (unsigned)row[e];
            if (r < (unsigned)N) {
                g_csr[pos]  = (int)r;
                g_csrc[pos] = g_dinv[r] * g_dinv[c];
            } else {
                g_csr[pos]  = 0;
                g_csrc[pos] = 0.0f;
            }
        }
    }
}

// ---------------------------------------------------------------------------
// GEMM  H = ACT(Xsrc) @ W  via packed fma.rn.f32x2.
// Tile 64 nodes x 128 cols, 256 threads, K chunked by 64.
#define GSM_W  0
#define GSM_X  32768
#define GSM_DYN 65536

__global__ __launch_bounds__(256) void k_gemm(const float* __restrict__ Xin,
                                              int layer,
                                              const float* __restrict__ bprev,
                                              const float* __restrict__ W,
                                              int N)
{
    extern __shared__ char sm[];
    const int t = threadIdx.x;
    const int c = t & 31;
    const int r = t >> 5;
    const int node0 = blockIdx.x * 64;

    ull acc01[8], acc23[8];
#pragma unroll
    for (int i = 0; i < 8; i++) { acc01[i] = 0ull; acc23[i] = 0ull; }

    for (int k0 = 0; k0 < 128; k0 += 64) {
        {
            const float4* src = (const float4*)(W + (size_t)k0 * 128);
            float4* dst = (float4*)(sm + GSM_W);
            for (int q = t; q < 64 * 32; q += 256) dst[q] = src[q];
        }
        {
            ull* Xd = (ull*)(sm + GSM_X);
            for (int q = t; q < 64 * 16; q += 256) {
                int n = q >> 4, kq = q & 15;
                int gn = node0 + n;
                float4 v = make_float4(0.f, 0.f, 0.f, 0.f);
                if (gn < N) {
                    if (layer == 0) {
                        v = *(const float4*)(Xin + (size_t)gn * 128 + k0 + kq * 4);
                    } else {
                        float4 a = *(const float4*)(g_agg + (size_t)gn * 128 + k0 + kq * 4);
                        float4 bb = *(const float4*)(bprev + k0 + kq * 4);
                        v.x = elu1(a.x + bb.x); v.y = elu1(a.y + bb.y);
                        v.z = elu1(a.z + bb.z); v.w = elu1(a.w + bb.w);
                    }
                }
                int base = n * 64 + kq * 4;
                Xd[base + 0] = dupf(v.x);
                Xd[base + 1] = dupf(v.y);
                Xd[base + 2] = dupf(v.z);
                Xd[base + 3] = dupf(v.w);
            }
        }
        __syncthreads();

        const ull* W2 = (const ull*)(sm + GSM_W);
        const ull* Xd = (const ull*)(sm + GSM_X);

#pragma unroll 4
        for (int kk = 0; kk < 64; kk++) {
            ull w01 = W2[kk * 64 + c * 2];
            ull w23 = W2[kk * 64 + c * 2 + 1];
            const ull* xr = Xd + (r * 8) * 64 + kk;
#pragma unroll
            for (int i = 0; i < 8; i++) {
                ull xx = xr[i * 64];
                fma2(acc01[i], xx, w01);
                fma2(acc23[i], xx, w23);
            }
        }
        __syncthreads();
    }

#pragma unroll
    for (int i = 0; i < 8; i++) {
        int gn = node0 + r * 8 + i;
        if (gn < N) {
            float4 v = make_float4(
                __uint_as_float((unsigned)(acc01[i] & 0xffffffffu)),
                __uint_as_float((unsigned)(acc01[i] >> 32)),
                __uint_as_float((unsigned)(acc23[i] & 0xffffffffu)),
                __uint_as_float((unsigned)(acc23[i] >> 32)));
            *(float4*)(g_h + (size_t)gn * 128 + c * 4) = v;
        }
    }
}

// ---------------------------------------------------------------------------
// CSR gather, shfl-free: one warp per node. Edge ids+coefs read via uniform
// (warp-broadcast, L1-cached) loads; 4 independent row reads in flight.
__global__ void k_gather(int N)
{
    int v = (blockIdx.x * blockDim.x + threadIdx.x) >> 5;
    int lane = threadIdx.x & 31;
    if (v >= N) return;

    float dv = g_dinv[v];
    float4 acc = ((const float4*)(g_h + (size_t)v * 128))[lane];
    float d2 = dv * dv;
    acc.x *= d2; acc.y *= d2; acc.z *= d2; acc.w *= d2;

    const int start = g_off[v];
    const int deg   = g_degi[v];
    int j = 0;

    for (; j + 4 <= deg; j += 4) {
        int   u0 = __ldg(&g_csr[start + j + 0]);
        int   u1 = __ldg(&g_csr[start + j + 1]);
        int   u2 = __ldg(&g_csr[start + j + 2]);
        int   u3 = __ldg(&g_csr[start + j + 3]);
        float c0 = __ldg(&g_csrc[start + j + 0]);
        float c1 = __ldg(&g_csrc[start + j + 1]);
        float c2 = __ldg(&g_csrc[start + j + 2]);
        float c3 = __ldg(&g_csrc[start + j + 3]);
        float4 h0 = ((const float4*)(g_h + (size_t)u0 * 128))[lane];
        float4 h1 = ((const float4*)(g_h + (size_t)u1 * 128))[lane];
        float4 h2 = ((const float4*)(g_h + (size_t)u2 * 128))[lane];
        float4 h3 = ((const float4*)(g_h + (size_t)u3 * 128))[lane];
        acc.x = fmaf(h0.x, c0, fmaf(h1.x, c1, fmaf(h2.x, c2, fmaf(h3.x, c3, acc.x))));
        acc.y = fmaf(h0.y, c0, fmaf(h1.y, c1, fmaf(h2.y, c2, fmaf(h3.y, c3, acc.y))));
        acc.z = fmaf(h0.z, c0, fmaf(h1.z, c1, fmaf(h2.z, c2, fmaf(h3.z, c3, acc.z))));
        acc.w = fmaf(h0.w, c0, fmaf(h1.w, c1, fmaf(h2.w, c2, fmaf(h3.w, c3, acc.w))));
    }
    for (; j < deg; j++) {
        int   u = __ldg(&g_csr[start + j]);
        float cf = __ldg(&g_csrc[start + j]);
        float4 hv = ((const float4*)(g_h + (size_t)u * 128))[lane];
        acc.x = fmaf(hv.x, cf, acc.x);
        acc.y = fmaf(hv.y, cf, acc.y);
        acc.z = fmaf(hv.z, cf, acc.z);
        acc.w = fmaf(hv.w, cf, acc.w);
    }
    ((float4*)(g_agg + (size_t)v * 128))[lane] = acc;
}

// ---------------------------------------------------------------------------
__global__ void k_pool(const float* __restrict__ b2, int N)
{
    int j = threadIdx.x;   // 128 threads
    float bj = b2[j];
    float s = 0.0f;
    for (int n = blockIdx.x; n < N; n += gridDim.x)
        s += elu1(g_agg[(size_t)n * 128 + j] + bj);
    atomicAdd(&g_pooled[j], s);
}

__global__ void k_final(const float* __restrict__ lin_w,
                        const float* __restrict__ lin_b,
                        float* __restrict__ out, int N)
{
    int j = threadIdx.x;
    if (j < 24) {
        float invn = 1.0f / (float)N;
        float s = lin_b[j];
#pragma unroll 8
        for (int k = 0; k < 128; k++)
            s += g_pooled[k] * invn * lin_w[k * 24 + j];
        out[j] = s;
    }
}

// ---------------------------------------------------------------------------
extern "C" void kernel_launch(void* const* d_in, const int* in_sizes, int n_in,
                              void* d_out, int out_size)
{
    // ---- Input identification: exact sizes (unit-agnostic), ignore extras.
    int unit = 1;
    {
        bool has24 = false, has96 = false;
        for (int i = 0; i < n_in; i++) {
            if (in_sizes[i] == 24) has24 = true;
            if (in_sizes[i] == 96) has96 = true;
        }
        if (!has24 && has96) unit = 4;
    }

    const float* x = nullptr;  const int* eidx = nullptr;
    const float* Ws[3] = {nullptr,nullptr,nullptr};
    const float* bs[3] = {nullptr,nullptr,nullptr};
    const float* lin_w = nullptr; const float* lin_b = nullptr;
    int iW = 0, ib = 0;

    for (int i = 0; i < n_in; i++) {
        long s = (long)in_sizes[i] / unit;
        if      (s == 12800000 && !x)      x     = (const float*)d_in[i];
        else if (s == 1200000  && !eidx)   eidx  = (const int*)  d_in[i];
        else if (s == 16384 && iW < 3)     Ws[iW++] = (const float*)d_in[i];
        else if (s == 3072  && !lin_w)     lin_w = (const float*)d_in[i];
        else if (s == 128   && ib < 3)     bs[ib++] = (const float*)d_in[i];
        else if (s == 24    && !lin_b)     lin_b = (const float*)d_in[i];
    }
    if (!x || !eidx || iW < 3 || ib < 3 || !lin_w || !lin_b) {
        int order[32];
        int m = (n_in < 32) ? n_in : 32;
        for (int i = 0; i < m; i++) order[i] = i;
        for (int i = 0; i < m; i++) {
            int best = i;
            for (int j = i + 1; j < m; j++)
                if (in_sizes[order[j]] > in_sizes[order[best]]) best = j;
            int tmp = order[best];
            for (int j = best; j > i; j--) order[j] = order[j - 1];
            order[i] = tmp;
        }
        if (m < 10) return;
        x     = (const float*)d_in[order[0]];
        eidx  = (const int*)  d_in[order[1]];
        Ws[0] = (const float*)d_in[order[2]];
        Ws[1] = (const float*)d_in[order[3]];
        Ws[2] = (const float*)d_in[order[4]];
        lin_w = (const float*)d_in[order[5]];
        bs[0] = (const float*)d_in[order[6]];
        bs[1] = (const float*)d_in[order[7]];
        bs[2] = (const float*)d_in[order[8]];
        lin_b = (const float*)d_in[order[9]];
    }
    float* out = (float*)d_out;

    const int N = 100000;
    const int E = 600000;
    const int* e_row = eidx;
    const int* e_col = eidx + E;

    cudaFuncSetAttribute(k_gemm,
                         cudaFuncAttributeMaxDynamicSharedMemorySize, GSM_DYN);

    // zero g_degi / g_pooled via async memsets (graph-capturable, no kernel)
    void* p_degi = nullptr; void* p_pool = nullptr;
    cudaGetSymbolAddress(&p_degi, g_degi);
    cudaGetSymbolAddress(&p_pool, g_pooled);
    cudaMemsetAsync(p_degi, 0, NMAX * sizeof(int));
    cudaMemsetAsync(p_pool, 0, HIDDIM * sizeof(float));

    // CSR build
    k_count<<<(E + 255) / 256, 256>>>(e_col, E, N);
    k_scan_a<<<NBLK, 256>>>(N);
    k_scan_b<<<1, 512>>>();
    k_scan_c<<<(N + 255) / 256, 256>>>(N);
    k_fill<<<(E + 255) / 256, 256>>>(e_row, e_col, E, N);

    const int gemm_blocks   = (N + 63) / 64;     // 1563
    const int gather_blocks = (N + 7) / 8;

    for (int l = 0; l < 3; l++) {
        k_gemm<<<gemm_blocks, 256, GSM_DYN>>>(x, l, l > 0 ? bs[l - 1] : nullptr,
                                              Ws[l], N);
        k_gather<<<gather_blocks, 256>>>(N);
    }

    k_pool<<<512, 128>>>(bs[2], N);
    k_final<<<1, 32>>>(lin_w, lin_b, out, N);
}

// round 12
// speedup vs baseline: 1.2898x; 1.1595x over previous
#include <cuda_runtime.h>
#include <cuda_bf16.h>
#include <math.h>
#include <stdint.h>

#define NMAX   100000
#define EMAX   600000
#define HIDDIM 128
#define NBLK   ((NMAX + 255) / 256)   // 391 scan blocks

typedef unsigned long long ull;

// Scratch (device globals)
__device__ int   g_degi[NMAX];
__device__ int   g_loc[NMAX];
__device__ int   g_bsum[NBLK];
__device__ int   g_off[NMAX];
__device__ int   g_cursor[NMAX];
__device__ uint2 g_csrp[EMAX];     // (source id, coef bits) per incoming edge
__device__ float g_dinv[NMAX];
__device__ uint2 g_hb[(size_t)NMAX * 32];   // H in bf16: row = 32 uint2 = 256B
__device__ float g_agg[(size_t)NMAX * HIDDIM];
__device__ float g_pooled[HIDDIM];

__device__ __forceinline__ float elu1(float x) { return x > 0.0f ? x : expm1f(x); }

// packed f32x2 fma: d = a*b + d   (sm_100+ baseline PTX)
__device__ __forceinline__ void fma2(ull& d, ull a, ull b)
{
    asm("fma.rn.f32x2 %0, %1, %2, %0;" : "+l"(d) : "l"(a), "l"(b));
}
__device__ __forceinline__ ull dupf(float x)
{
    unsigned u = __float_as_uint(x);
    return ((ull)u << 32) | u;
}
// fused bf16-row multiply-accumulate: acc += bf16x4(r) * cf
__device__ __forceinline__ void bfma(float4& a, uint2 r, float cf)
{
    float2 f0 = __bfloat1622float2(*(const __nv_bfloat162*)&r.x);
    float2 f1 = __bfloat1622float2(*(const __nv_bfloat162*)&r.y);
    a.x = fmaf(f0.x, cf, a.x); a.y = fmaf(f0.y, cf, a.y);
    a.z = fmaf(f1.x, cf, a.z); a.w = fmaf(f1.y, cf, a.w);
}

// ---------------------------------------------------------------------------
__global__ void k_count(const int* __restrict__ col, int E, int N)
{
    int e = blockIdx.x * blockDim.x + threadIdx.x;
    if (e < E) {
        unsigned c = (unsigned)col[e];
        if (c < (unsigned)N) atomicAdd(&g_degi[c], 1);
    }
}

__global__ void k_scan_a(int N)
{
    __shared__ int s[256];
    int tid = threadIdx.x;
    int i = blockIdx.x * 256 + tid;
    int v = (i < N) ? g_degi[i] : 0;
    s[tid] = v;
    __syncthreads();
    int acc = v;
#pragma unroll
    for (int d = 1; d < 256; d <<= 1) {
        int add = (tid >= d) ? s[tid - d] : 0;
        __syncthreads();
        acc += add;
        s[tid] = acc;
        __syncthreads();
    }
    if (i < N) g_loc[i] = acc - v;
    if (tid == 255) g_bsum[blockIdx.x] = acc;
}

__global__ void k_scan_b(void)
{
    __shared__ int s[512];
    int tid = threadIdx.x;
    int v = (tid < NBLK) ? g_bsum[tid] : 0;
    s[tid] = v;
    __syncthreads();
    int acc = v;
#pragma unroll
    for (int d = 1; d < 512; d <<= 1) {
        int add = (tid >= d) ? s[tid - d] : 0;
        __syncthreads();
        acc += add;
        s[tid] = acc;
        __syncthreads();
    }
    if (tid < NBLK) g_bsum[tid] = acc - v;
}

__global__ void k_scan_c(int N)
{
    int i = blockIdx.x * blockDim.x + threadIdx.x;
    if (i < N) {
        int o = g_loc[i] + g_bsum[i >> 8];
        g_off[i] = o;
        g_cursor[i] = o;
        g_dinv[i] = rsqrtf(1.0f + (float)g_degi[i]);
    }
}

// fill CSR: packed (source id, coefficient) — dinv ready here
__global__ void k_fill(const int* __restrict__ row,
                       const int* __restrict__ col, int E, int N)
{
    int e = blockIdx.x * blockDim.x + threadIdx.x;
    if (e < E) {
        unsigned c = (unsigned)col[e];
        if (c < (unsigned)N) {
            int pos = atomicAdd(&g_cursor[c], 1);
            unsigned r = (unsigned)row[e];
            uint2 p;
            if (r < (unsigned)N) {
                p.x = r;
                p.y = __float_as_uint(g_dinv[r] * g_dinv[c]);
            } else {
                p.x = 0; p.y = 0;
            }
            g_csrp[pos] = p;
        }
    }
}

// ---------------------------------------------------------------------------
// GEMM  H = ACT(Xsrc) @ W  via packed fma.rn.f32x2; epilogue emits bf16 H.
#define GSM_W  0
#define GSM_X  32768
#define GSM_DYN 65536

__global__ __launch_bounds__(256) void k_gemm(const float* __restrict__ Xin,
                                              int layer,
                                              const float* __restrict__ bprev,
                                              const float* __restrict__ W,
                                              int N)
{
    extern __shared__ char sm[];
    const int t = threadIdx.x;
    const int c = t & 31;
    const int r = t >> 5;
    const int node0 = blockIdx.x * 64;

    ull acc01[8], acc23[8];
#pragma unroll
    for (int i = 0; i < 8; i++) { acc01[i] = 0ull; acc23[i] = 0ull; }

    for (int k0 = 0; k0 < 128; k0 += 64) {
        {
            const float4* src = (const float4*)(W + (size_t)k0 * 128);
            float4* dst = (float4*)(sm + GSM_W);
            for (int q = t; q < 64 * 32; q += 256) dst[q] = src[q];
        }
        {
            ull* Xd = (ull*)(sm + GSM_X);
            for (int q = t; q < 64 * 16; q += 256) {
                int n = q >> 4, kq = q & 15;
                int gn = node0 + n;
                float4 v = make_float4(0.f, 0.f, 0.f, 0.f);
                if (gn < N) {
                    if (layer == 0) {
                        v = *(const float4*)(Xin + (size_t)gn * 128 + k0 + kq * 4);
                    } else {
                        float4 a = *(const float4*)(g_agg + (size_t)gn * 128 + k0 + kq * 4);
                        float4 bb = *(const float4*)(bprev + k0 + kq * 4);
                        v.x = elu1(a.x + bb.x); v.y = elu1(a.y + bb.y);
                        v.z = elu1(a.z + bb.z); v.w = elu1(a.w + bb.w);
                    }
                }
                int base = n * 64 + kq * 4;
                Xd[base + 0] = dupf(v.x);
                Xd[base + 1] = dupf(v.y);
                Xd[base + 2] = dupf(v.z);
                Xd[base + 3] = dupf(v.w);
            }
        }
        __syncthreads();

        const ull* W2 = (const ull*)(sm + GSM_W);
        const ull* Xd = (const ull*)(sm + GSM_X);

#pragma unroll 4
        for (int kk = 0; kk < 64; kk++) {
            ull w01 = W2[kk * 64 + c * 2];
            ull w23 = W2[kk * 64 + c * 2 + 1];
            const ull* xr = Xd + (r * 8) * 64 + kk;
#pragma unroll
            for (int i = 0; i < 8; i++) {
                ull xx = xr[i * 64];
                fma2(acc01[i], xx, w01);
                fma2(acc23[i], xx, w23);
            }
        }
        __syncthreads();
    }

    // epilogue: unpack, convert to bf16x2 pairs -> g_hb (8B/lane, coalesced)
#pragma unroll
    for (int i = 0; i < 8; i++) {
        int gn = node0 + r * 8 + i;
        if (gn < N) {
            float x0 = __uint_as_float((unsigned)(acc01[i] & 0xffffffffu));
            float x1 = __uint_as_float((unsigned)(acc01[i] >> 32));
            float x2 = __uint_as_float((unsigned)(acc23[i] & 0xffffffffu));
            float x3 = __uint_as_float((unsigned)(acc23[i] >> 32));
            __nv_bfloat162 lo = __floats2bfloat162_rn(x0, x1);
            __nv_bfloat162 hi = __floats2bfloat162_rn(x2, x3);
            uint2 p;
            p.x = *(const unsigned*)&lo;
            p.y = *(const unsigned*)&hi;
            g_hb[(size_t)gn * 32 + c] = p;
        }
    }
}

// ---------------------------------------------------------------------------
// CSR gather over bf16 H (L2-resident, 25.6MB): one warp per node,
// packed (id,coef) metadata, 4 independent 256B row reads in flight.
__global__ void k_gather(int N)
{
    int v = (blockIdx.x * blockDim.x + threadIdx.x) >> 5;
    int lane = threadIdx.x & 31;
    if (v >= N) return;

    float dv = g_dinv[v];
    float d2 = dv * dv;

    uint2 sp = g_hb[(size_t)v * 32 + lane];
    float2 s0 = __bfloat1622float2(*(const __nv_bfloat162*)&sp.x);
    float2 s1 = __bfloat1622float2(*(const __nv_bfloat162*)&sp.y);
    float4 acc = make_float4(s0.x * d2, s0.y * d2, s1.x * d2, s1.y * d2);

    const int start = g_off[v];
    const int deg   = g_degi[v];
    int j = 0;

    for (; j + 4 <= deg; j += 4) {
        uint2 e0 = __ldg(&g_csrp[start + j + 0]);
        uint2 e1 = __ldg(&g_csrp[start + j + 1]);
        uint2 e2 = __ldg(&g_csrp[start + j + 2]);
        uint2 e3 = __ldg(&g_csrp[start + j + 3]);
        uint2 r0 = g_hb[(size_t)e0.x * 32 + lane];
        uint2 r1 = g_hb[(size_t)e1.x * 32 + lane];
        uint2 r2 = g_hb[(size_t)e2.x * 32 + lane];
        uint2 r3 = g_hb[(size_t)e3.x * 32 + lane];
        bfma(acc, r0, __uint_as_float(e0.y));
        bfma(acc, r1, __uint_as_float(e1.y));
        bfma(acc, r2, __uint_as_float(e2.y));
        bfma(acc, r3, __uint_as_float(e3.y));
    }
    for (; j < deg; j++) {
        uint2 e = __ldg(&g_csrp[start + j]);
        uint2 rr = g_hb[(size_t)e.x * 32 + lane];
        bfma(acc, rr, __uint_as_float(e.y));
    }
    ((float4*)(g_agg + (size_t)v * 128))[lane] = acc;
}

// ---------------------------------------------------------------------------
__global__ void k_pool(const float* __restrict__ b2, int N)
{
    int j = threadIdx.x;   // 128 threads
    float bj = b2[j];
    float s = 0.0f;
    for (int n = blockIdx.x; n < N; n += gridDim.x)
        s += elu1(g_agg[(size_t)n * 128 + j] + bj);
    atomicAdd(&g_pooled[j], s);
}

__global__ void k_final(const float* __restrict__ lin_w,
                        const float* __restrict__ lin_b,
                        float* __restrict__ out, int N)
{
    int j = threadIdx.x;
    if (j < 24) {
        float invn = 1.0f / (float)N;
        float s = lin_b[j];
#pragma unroll 8
        for (int k = 0; k < 128; k++)
            s += g_pooled[k] * invn * lin_w[k * 24 + j];
        out[j] = s;
    }
}

// ---------------------------------------------------------------------------
extern "C" void kernel_launch(void* const* d_in, const int* in_sizes, int n_in,
                              void* d_out, int out_size)
{
    // ---- Input identification: exact sizes (unit-agnostic), ignore extras.
    int unit = 1;
    {
        bool has24 = false, has96 = false;
        for (int i = 0; i < n_in; i++) {
            if (in_sizes[i] == 24) has24 = true;
            if (in_sizes[i] == 96) has96 = true;
        }
        if (!has24 && has96) unit = 4;
    }

    const float* x = nullptr;  const int* eidx = nullptr;
    const float* Ws[3] = {nullptr,nullptr,nullptr};
    const float* bs[3] = {nullptr,nullptr,nullptr};
    const float* lin_w = nullptr; const float* lin_b = nullptr;
    int iW = 0, ib = 0;

    for (int i = 0; i < n_in; i++) {
        long s = (long)in_sizes[i] / unit;
        if      (s == 12800000 && !x)      x     = (const float*)d_in[i];
        else if (s == 1200000  && !eidx)   eidx  = (const int*)  d_in[i];
        else if (s == 16384 && iW < 3)     Ws[iW++] = (const float*)d_in[i];
        else if (s == 3072  && !lin_w)     lin_w = (const float*)d_in[i];
        else if (s == 128   && ib < 3)     bs[ib++] = (const float*)d_in[i];
        else if (s == 24    && !lin_b)     lin_b = (const float*)d_in[i];
    }
    if (!x || !eidx || iW < 3 || ib < 3 || !lin_w || !lin_b) {
        int order[32];
        int m = (n_in < 32) ? n_in : 32;
        for (int i = 0; i < m; i++) order[i] = i;
        for (int i = 0; i < m; i++) {
            int best = i;
            for (int j = i + 1; j < m; j++)
                if (in_sizes[order[j]] > in_sizes[order[best]]) best = j;
            int tmp = order[best];
            for (int j = best; j > i; j--) order[j] = order[j - 1];
            order[i] = tmp;
        }
        if (m < 10) return;
        x     = (const float*)d_in[order[0]];
        eidx  = (const int*)  d_in[order[1]];
        Ws[0] = (const float*)d_in[order[2]];
        Ws[1] = (const float*)d_in[order[3]];
        Ws[2] = (const float*)d_in[order[4]];
        lin_w = (const float*)d_in[order[5]];
        bs[0] = (const float*)d_in[order[6]];
        bs[1] = (const float*)d_in[order[7]];
        bs[2] = (const float*)d_in[order[8]];
        lin_b = (const float*)d_in[order[9]];
    }
    float* out = (float*)d_out;

    const int N = 100000;
    const int E = 600000;
    const int* e_row = eidx;
    const int* e_col = eidx + E;

    cudaFuncSetAttribute(k_gemm,
                         cudaFuncAttributeMaxDynamicSharedMemorySize, GSM_DYN);

    // zero g_degi / g_pooled via async memsets (graph-capturable, no kernel)
    void* p_degi = nullptr; void* p_pool = nullptr;
    cudaGetSymbolAddress(&p_degi, g_degi);
    cudaGetSymbolAddress(&p_pool, g_pooled);
    cudaMemsetAsync(p_degi, 0, NMAX * sizeof(int));
    cudaMemsetAsync(p_pool, 0, HIDDIM * sizeof(float));

    // CSR build
    k_count<<<(E + 255) / 256, 256>>>(e_col, E, N);
    k_scan_a<<<NBLK, 256>>>(N);
    k_scan_b<<<1, 512>>>();
    k_scan_c<<<(N + 255) / 256, 256>>>(N);
    k_fill<<<(E + 255) / 256, 256>>>(e_row, e_col, E, N);

    const int gemm_blocks   = (N + 63) / 64;     // 1563
    const int gather_blocks = (N + 7) / 8;

    for (int l = 0; l < 3; l++) {
        k_gemm<<<gemm_blocks, 256, GSM_DYN>>>(x, l, l > 0 ? bs[l - 1] : nullptr,
                                              Ws[l], N);
        k_gather<<<gather_blocks, 256>>>(N);
    }

    k_pool<<<512, 128>>>(bs[2], N);
    k_final<<<1, 32>>>(lin_w, lin_b, out, N);
}